// round 5
// baseline (speedup 1.0000x reference)
#include <cuda_runtime.h>
#include <cuda_bf16.h>

// Shapes fixed by the problem
#define N_   8
#define C_   256
#define HW_  16384
#define S_   16

// ---------------------------------------------------------------------------
// Lean relu-stream kernel: runs ONLY when gamma == 0 (exact algebra:
// relu(id + 0*out) = relu(id)).
// Grid MUST be 1024 x 256: 8.39M float4 = 8 iters x 4 slabs x 262144 threads.
// 4 independent LDG.128 batched per iter -> high MLP; __ldcs/__stcs since data
// is touched exactly once (no L2 reuse to preserve).
// ---------------------------------------------------------------------------
__global__ __launch_bounds__(256) void relu_stream_kernel(
    const float* __restrict__ rgb,
    const float* __restrict__ gamma_p,
    float* __restrict__ out)
{
    if (__ldg(gamma_p) != 0.0f) return;

    const float4* __restrict__ in4  = (const float4*)rgb;
    float4*       __restrict__ out4 = (float4*)out;

    const unsigned T = 1024u * 256u;                 // total threads = 262144
    unsigned i = blockIdx.x * 256u + threadIdx.x;

    #pragma unroll 1
    for (int k = 0; k < 8; k++) {
        float4 a = __ldcs(in4 + i);
        float4 b = __ldcs(in4 + i + T);
        float4 c = __ldcs(in4 + i + 2u * T);
        float4 d = __ldcs(in4 + i + 3u * T);
        a.x = fmaxf(a.x, 0.f); a.y = fmaxf(a.y, 0.f);
        a.z = fmaxf(a.z, 0.f); a.w = fmaxf(a.w, 0.f);
        b.x = fmaxf(b.x, 0.f); b.y = fmaxf(b.y, 0.f);
        b.z = fmaxf(b.z, 0.f); b.w = fmaxf(b.w, 0.f);
        c.x = fmaxf(c.x, 0.f); c.y = fmaxf(c.y, 0.f);
        c.z = fmaxf(c.z, 0.f); c.w = fmaxf(c.w, 0.f);
        d.x = fmaxf(d.x, 0.f); d.y = fmaxf(d.y, 0.f);
        d.z = fmaxf(d.z, 0.f); d.w = fmaxf(d.w, 0.f);
        __stcs(out4 + i,          a);
        __stcs(out4 + i + T,      b);
        __stcs(out4 + i + 2u * T, c);
        __stcs(out4 + i + 3u * T, d);
        i += 4u * T;
    }
}

// ---------------------------------------------------------------------------
// Fused full-path kernel: runs ONLY when gamma != 0 (never for this dataset's
// gamma==0, so it only pays early-exit cost; must stay CORRECT regardless).
// Self-contained: each block gathers S_rgb and recomputes h = S_rgb@W^T + b
// (redundant per block, but removes the separate prep launch).
// grid (HW/256, N), 256 threads, thread t owns q = blockIdx.x*256 + t.
// ---------------------------------------------------------------------------
__global__ __launch_bounds__(256) void fused_kernel(
    const float* __restrict__ rgb,
    const void*  __restrict__ idx_raw,
    const float* __restrict__ W,
    const float* __restrict__ b,
    const float* __restrict__ gamma_p,
    float* __restrict__ out)
{
    const float gamma = __ldg(gamma_p);
    if (gamma == 0.0f) return;       // handled by relu_stream_kernel

    __shared__ float Ssh[S_][C_];
    __shared__ float Hsh[S_][C_];

    const int n = blockIdx.y;
    const int t = threadIdx.x;       // 0..255 = channel c = out-dim d
    const int q = blockIdx.x * 256 + t;

    // Index dtype detection (int64 vs int32). Probe only the first 64 int64
    // words = 512B, within-bounds for EITHER dtype (int32 buf = 512B).
    // If data is int32, a paired int64 has hi-word = next index; P(all 64
    // hi-words == 0) = (1/16384)^64 ~ 0, so misdetection is impossible.
    const long long* p64 = (const long long*)idx_raw;
    const int*       p32 = (const int*)idx_raw;
    bool is64 = true;
    for (int i = 0; i < 64; i++) {
        long long v = p64[i];
        if (v < 0 || v >= HW_) { is64 = false; break; }
    }

    const float* rgbn = rgb + (size_t)n * C_ * HW_;

    // Gather S_rgb: thread t = channel c
    #pragma unroll
    for (int s = 0; s < S_; s++) {
        int qs = is64 ? (int)p64[n * S_ + s] : p32[n * S_ + s];
        Ssh[s][t] = rgbn[t * HW_ + qs];
    }
    __syncthreads();

    // h[s][d] = b[d] + sum_c Srgb[s][c] * W[d][c]  (thread t = d)
    {
        float hv[S_];
        #pragma unroll
        for (int s = 0; s < S_; s++) hv[s] = b[t];
        for (int c = 0; c < C_; c++) {
            float w = W[t * C_ + c];
            #pragma unroll
            for (int s = 0; s < S_; s++) hv[s] = fmaf(Ssh[s][c], w, hv[s]);
        }
        #pragma unroll
        for (int s = 0; s < S_; s++) Hsh[s][t] = hv[s];
    }
    __syncthreads();

    float*       outn = out + (size_t)n * C_ * HW_;

    // Phase 1: adj[s] = sum_c x[q,c] * S_rgb[s,c]  (loads coalesced along q)
    float acc[S_];
    #pragma unroll
    for (int s = 0; s < S_; s++) acc[s] = 0.0f;
    for (int c = 0; c < C_; c++) {
        float v = rgbn[c * HW_ + q];
        #pragma unroll
        for (int s = 0; s < S_; s++) acc[s] = fmaf(v, Ssh[s][c], acc[s]);
    }

    // Phase 2: out[c] = relu(id + gamma * sum_s adj[s] * h[s,c])
    for (int c = 0; c < C_; c++) {
        float o = 0.0f;
        #pragma unroll
        for (int s = 0; s < S_; s++) o = fmaf(acc[s], Hsh[s][c], o);
        float idv = rgbn[c * HW_ + q];           // L1/L2 hit (same tile)
        outn[c * HW_ + q] = fmaxf(fmaf(gamma, o, idv), 0.0f);
    }
}

extern "C" void kernel_launch(void* const* d_in, const int* in_sizes, int n_in,
                              void* d_out, int out_size)
{
    const float* rgb   = (const float*)d_in[0];
    const void*  idx   = d_in[1];                 // int64 or int32, device-detected
    const float* W     = (const float*)d_in[2];
    const float* b     = (const float*)d_in[3];
    const float* gamma = (const float*)d_in[4];
    float*       out   = (float*)d_out;

    // gamma==0 hot path: single-wave stream kernel (grid fixed at 1024x256
    // to match the 8-iter x 4-slab unroll; see kernel comment).
    relu_stream_kernel<<<1024, 256>>>(rgb, gamma, out);

    // gamma!=0 path: one self-contained kernel (early-exits when gamma==0)
    dim3 grid(HW_ / 256, N_);
    fused_kernel<<<grid, 256>>>(rgb, idx, W, b, gamma, out);
}